// round 1
// baseline (speedup 1.0000x reference)
#include <cuda_runtime.h>
#include <math.h>

#define KKEY   2048
#define CFEAT  128
#define M_GRID 216
#define NPROP  48
#define NPTS   (NPROP*M_GRID)      // 10368 per batch
#define NTOT   (2*NPTS)            // 20736
#define QDIM   (128*M_GRID)        // 27648
#define KSPLIT 27
#define KCHUNK 1024

// ---------------- scratch (static device globals; no allocs) ----------------
__device__ float g_new_xyz[NTOT*3];
__device__ float g_pre[2*2*KKEY*64];          // [scale][b][k][o]
__device__ float g_pooled[2*NPROP*QDIM];      // rows 96 x 27648, q = co*216+mm
__device__ float g_partial[KSPLIT*96*256];

// ---------------- kernel A: grid transform -> new_xyz ----------------
__global__ void __launch_bounds__(256) kA(const float* __restrict__ prop,
                                          const float* __restrict__ gnoise) {
    int t = blockIdx.x*256 + threadIdx.x;
    if (t >= NTOT) return;
    int b = t / NPTS, r = t % NPTS;
    int n = r / M_GRID, mm = r % M_GRID;
    const float* p = prop + (size_t)(b*NPROP + n)*7;
    const float* g = gnoise + ((size_t)(b*NPROP + n)*M_GRID + mm)*3;
    float gx = g[0]*p[3], gy = g[1]*p[4], gz = g[2]*p[5];
    float c = cosf(p[6]), s = sinf(p[6]);
    float X = c*gx - s*gy + p[0];
    float Y = s*gx + c*gy + p[1];
    float Z = gz + p[2];
    float* o = g_new_xyz + (size_t)t*3;
    o[0] = X; o[1] = Y; o[2] = Z;
}

// ---------------- kernel B: pre[k][o] = W0[:,3:] . feats[:,k] ----------------
__global__ void __launch_bounds__(256) kB(const float* __restrict__ feats,
                                          const float* __restrict__ w0,   // scale0 layer0 (64,131)
                                          const float* __restrict__ w1) { // scale1 layer0 (64,131)
    __shared__ float Ws[CFEAT*64];   // Ws[c][o]
    int sb = blockIdx.y; int sc = sb >> 1, b = sb & 1;
    const float* W = sc ? w1 : w0;
    for (int i = threadIdx.x; i < CFEAT*64; i += 256) {
        int c = i >> 6, o = i & 63;
        Ws[i] = W[o*131 + 3 + c];
    }
    __syncthreads();
    int o  = threadIdx.x & 63;
    int kk = threadIdx.x >> 6;
    int kbase = blockIdx.x * 32;
    const float* fb = feats + (size_t)b*CFEAT*KKEY;
    for (int kl = kk; kl < 32; kl += 4) {
        int k = kbase + kl;
        float acc = 0.f;
        #pragma unroll 8
        for (int c = 0; c < CFEAT; c++)
            acc = fmaf(__ldg(&fb[(size_t)c*KKEY + k]), Ws[c*64 + o], acc);
        g_pre[(((size_t)(sc*2 + b)*KKEY + k) << 6) + o] = acc;
    }
}

// ---------------- kernel C: ball query + 2-layer MLP + maxpool ----------------
// dyn smem layout (floats):
//   kx[2048] ky[2048] kz[2048]                (0    .. 6144)
//   w1t[2][64*65]  (W1 transposed, pitch 65)  (6144 .. 14464)
//   wxyz[2][3][64]                            (14464.. 14848)
//   b0s[2][64] b1s[2][64]                     (14848.. 15104)
//   h0buf[8][256]  ([j][s] interleave, s=0..3)(15104.. 17152)
//   idx1[8][32] idx0[8][16] (ints)            (17152.. 17536)
#define KC_SMEM_WORDS 17536
__global__ void __launch_bounds__(256) kC(
    const float* __restrict__ kxyzg,
    const float* __restrict__ w00, const float* __restrict__ b00,
    const float* __restrict__ w01, const float* __restrict__ b01,
    const float* __restrict__ w10, const float* __restrict__ b10,
    const float* __restrict__ w11, const float* __restrict__ b11)
{
    extern __shared__ float sm[];
    float* kxs  = sm;
    float* kys  = sm + 2048;
    float* kzs  = sm + 4096;
    float* w1t  = sm + 6144;
    float* wxyz = sm + 14464;
    float* b0s  = sm + 14848;
    float* b1s  = sm + 14976;
    float* h0b  = sm + 15104;
    int*   idx1 = (int*)(sm + 17152);
    int*   idx0 = (int*)(sm + 17408);

    const int b = blockIdx.x / 1296;         // 1296 blocks per batch (8 pts/block)

    // fill shared
    const float* kb = kxyzg + (size_t)b*KKEY*3;
    for (int i = threadIdx.x; i < KKEY; i += 256) {
        kxs[i] = kb[i*3]; kys[i] = kb[i*3+1]; kzs[i] = kb[i*3+2];
    }
    for (int i = threadIdx.x; i < 2*4096; i += 256) {
        int sc = i >> 12, t = i & 4095, o = t >> 6, j = t & 63;
        const float* W1 = sc ? w11 : w01;
        w1t[sc*4160 + j*65 + o] = W1[o*64 + j];
    }
    for (int i = threadIdx.x; i < 2*3*64; i += 256) {
        int sc = i / 192, t = i % 192, d = t / 64, o = t % 64;
        const float* W0 = sc ? w10 : w00;
        wxyz[i] = W0[o*131 + d];
    }
    if (threadIdx.x < 128) {
        int sc = threadIdx.x >> 6, o = threadIdx.x & 63;
        b0s[threadIdx.x] = (sc ? b10 : b00)[o];
        b1s[threadIdx.x] = (sc ? b11 : b01)[o];
    }
    __syncthreads();

    const int w = threadIdx.x >> 5, lane = threadIdx.x & 31;
    const int p  = blockIdx.x*8 + w;         // global point id
    const int rp = p % NPTS;
    const float px = g_new_xyz[(size_t)p*3], py = g_new_xyz[(size_t)p*3+1],
                pz = g_new_xyz[(size_t)p*3+2];
    const float pn = fmaf(px,px, fmaf(py,py, pz*pz));

    // ---- ordered ball query (ballot + prefix-popc ranking) ----
    const float R0 = 0.8f*0.8f, R1 = 1.6f*1.6f;
    int* l1 = idx1 + w*32;
    int* l0 = idx0 + w*16;
    int c0 = 0, c1 = 0;
    const unsigned lt = (1u << lane) - 1u;
    for (int base = 0; base < KKEY; base += 32) {
        int k = base + lane;
        float kx = kxs[k], ky = kys[k], kz = kzs[k];
        float kn  = fmaf(kx,kx, fmaf(ky,ky, kz*kz));
        float dot = fmaf(px,kx, fmaf(py,ky, pz*kz));
        float d2  = fmaf(-2.f, dot, pn + kn);
        bool v1 = d2 < R1, v0 = d2 < R0;
        unsigned m1 = __ballot_sync(0xffffffffu, v1);
        unsigned m0 = __ballot_sync(0xffffffffu, v0);
        if (c1 < 32 && m1) {
            if (v1) { int rk = c1 + __popc(m1 & lt); if (rk < 32) l1[rk] = k; }
            c1 = min(32, c1 + __popc(m1));
        }
        if (c0 < 16 && m0) {
            if (v0) { int rk = c0 + __popc(m0 & lt); if (rk < 16) l0[rk] = k; }
            c0 = min(16, c0 + __popc(m0));
        }
        if (c0 >= 16 && c1 >= 32) break;
    }
    __syncwarp();

    // ---- per-scale MLP + maxpool ----
    const int n  = rp / M_GRID, mm = rp % M_GRID;
    float* hb = h0b + w*256;

    #pragma unroll
    for (int sc = 0; sc < 2; sc++) {
        int cnt = sc ? c1 : c0;
        int* lst = sc ? l1 : l0;
        if (cnt == 0) { if (lane == 0) lst[0] = 0; cnt = 1; __syncwarp(); }

        const float* preb = g_pre + ((size_t)(sc*2 + b)*KKEY << 6);
        const float* wt = w1t + sc*4160;
        const float* wx = wxyz + sc*192;
        const float bias0a = b0s[sc*64 + lane],      bias0b = b0s[sc*64 + lane + 32];
        const float bias1a = b1s[sc*64 + lane],      bias1b = b1s[sc*64 + lane + 32];
        float mxa = 0.f, mxb = 0.f;

        for (int s0 = 0; s0 < cnt; s0 += 4) {
            // layer 0 for 4 samples (tail replicates sample 0 == reference padding)
            #pragma unroll
            for (int s = 0; s < 4; s++) {
                int si = s0 + s;
                int k  = lst[si < cnt ? si : 0];
                float rx = kxs[k]-px, ry = kys[k]-py, rz = kzs[k]-pz;
                const float* pr = preb + ((size_t)k << 6);
                float va = pr[lane] + bias0a;
                va = fmaf(rx, wx[lane],        va);
                va = fmaf(ry, wx[64 + lane],   va);
                va = fmaf(rz, wx[128 + lane],  va);
                hb[(lane << 2) | s] = fmaxf(va, 0.f);
                float vb = pr[lane + 32] + bias0b;
                vb = fmaf(rx, wx[lane + 32],       vb);
                vb = fmaf(ry, wx[64 + lane + 32],  vb);
                vb = fmaf(rz, wx[128 + lane + 32], vb);
                hb[((lane + 32) << 2) | s] = fmaxf(vb, 0.f);
            }
            __syncwarp();
            // layer 1: 2 outputs x 4 samples per lane
            float a0 = bias1a, a1 = bias1a, a2 = bias1a, a3 = bias1a;
            float e0 = bias1b, e1 = bias1b, e2 = bias1b, e3 = bias1b;
            #pragma unroll
            for (int j = 0; j < 64; j++) {
                float wA = wt[j*65 + lane];
                float wB = wt[j*65 + lane + 32];
                float4 h = *(const float4*)(hb + (j << 2));
                a0 = fmaf(wA, h.x, a0); a1 = fmaf(wA, h.y, a1);
                a2 = fmaf(wA, h.z, a2); a3 = fmaf(wA, h.w, a3);
                e0 = fmaf(wB, h.x, e0); e1 = fmaf(wB, h.y, e1);
                e2 = fmaf(wB, h.z, e2); e3 = fmaf(wB, h.w, e3);
            }
            mxa = fmaxf(mxa, fmaxf(fmaxf(a0,a1), fmaxf(a2,a3)));
            mxb = fmaxf(mxb, fmaxf(fmaxf(e0,e1), fmaxf(e2,e3)));
            __syncwarp();
        }
        // relu(max) == max(relu) since mx init 0
        size_t row = (size_t)(b*NPROP + n);
        g_pooled[row*QDIM + (size_t)(sc*64 + lane)*M_GRID + mm]      = mxa;
        g_pooled[row*QDIM + (size_t)(sc*64 + lane + 32)*M_GRID + mm] = mxb;
    }
}

// ---------------- kernel D: K-split GEMM partial = pooled @ red_w0^T ----------------
__global__ void __launch_bounds__(256) kD(const float* __restrict__ w0) {
    __shared__ float xs[16*20];
    __shared__ float ws[64*20];
    const int tid = threadIdx.x;
    const int r  = tid & 15, cg = tid >> 4;
    const int rowbase = blockIdx.y * 16;
    const int colbase = blockIdx.x * 64;
    const int kz = blockIdx.z;
    float acc0 = 0.f, acc1 = 0.f, acc2 = 0.f, acc3 = 0.f;

    for (int kbb = 0; kbb < KCHUNK; kbb += 16) {
        int kg = kz*KCHUNK + kbb;
        {   // load x tile (16 rows x 16 k)
            int rr = tid >> 4, kk = tid & 15;
            xs[rr*20 + kk] = g_pooled[(size_t)(rowbase + rr)*QDIM + kg + kk];
        }
        for (int i = tid; i < 1024; i += 256) {   // w tile (64 cols x 16 k)
            int cc = i >> 4, kk = i & 15;
            ws[cc*20 + kk] = w0[(size_t)(colbase + cc)*QDIM + kg + kk];
        }
        __syncthreads();
        #pragma unroll
        for (int k4 = 0; k4 < 16; k4 += 4) {
            float4 xv  = *(const float4*)(xs + r*20 + k4);
            float4 w0v = *(const float4*)(ws + (cg*4 + 0)*20 + k4);
            float4 w1v = *(const float4*)(ws + (cg*4 + 1)*20 + k4);
            float4 w2v = *(const float4*)(ws + (cg*4 + 2)*20 + k4);
            float4 w3v = *(const float4*)(ws + (cg*4 + 3)*20 + k4);
            acc0 = fmaf(xv.x,w0v.x,acc0); acc0 = fmaf(xv.y,w0v.y,acc0);
            acc0 = fmaf(xv.z,w0v.z,acc0); acc0 = fmaf(xv.w,w0v.w,acc0);
            acc1 = fmaf(xv.x,w1v.x,acc1); acc1 = fmaf(xv.y,w1v.y,acc1);
            acc1 = fmaf(xv.z,w1v.z,acc1); acc1 = fmaf(xv.w,w1v.w,acc1);
            acc2 = fmaf(xv.x,w2v.x,acc2); acc2 = fmaf(xv.y,w2v.y,acc2);
            acc2 = fmaf(xv.z,w2v.z,acc2); acc2 = fmaf(xv.w,w2v.w,acc2);
            acc3 = fmaf(xv.x,w3v.x,acc3); acc3 = fmaf(xv.y,w3v.y,acc3);
            acc3 = fmaf(xv.z,w3v.z,acc3); acc3 = fmaf(xv.w,w3v.w,acc3);
        }
        __syncthreads();
    }
    int row = rowbase + r;
    float* pp = g_partial + ((size_t)kz*96 + row)*256 + colbase + cg*4;
    pp[0] = acc0; pp[1] = acc1; pp[2] = acc2; pp[3] = acc3;
}

// ---------------- kernel E: reduce partials + relu + 256x256 GEMM + relu ----------------
__global__ void __launch_bounds__(256) kE(const float* __restrict__ rb0,
                                          const float* __restrict__ rw1,
                                          const float* __restrict__ rb1,
                                          float* __restrict__ out) {
    __shared__ float h2s[256];
    __shared__ float w1s[256*33];
    const int row = blockIdx.x;
    const int o = threadIdx.x;
    float s = rb0[o];
    #pragma unroll
    for (int ks = 0; ks < KSPLIT; ks++)
        s += g_partial[((size_t)ks*96 + row)*256 + o];
    h2s[o] = fmaxf(s, 0.f);
    __syncthreads();

    float acc = rb1[o];
    for (int jt = 0; jt < 256; jt += 32) {
        for (int i = threadIdx.x; i < 8192; i += 256) {
            int oo = i >> 5, jj = i & 31;
            w1s[oo*33 + jj] = rw1[(size_t)oo*256 + jt + jj];
        }
        __syncthreads();
        #pragma unroll
        for (int jj = 0; jj < 32; jj++)
            acc = fmaf(h2s[jt + jj], w1s[o*33 + jj], acc);
        __syncthreads();
    }
    out[(size_t)row*256 + o] = fmaxf(acc, 0.f);
}

// ---------------- launch ----------------
extern "C" void kernel_launch(void* const* d_in, const int* in_sizes, int n_in,
                              void* d_out, int out_size) {
    const float* proposals = (const float*)d_in[0];
    const float* kxyz      = (const float*)d_in[1];
    const float* kfeat     = (const float*)d_in[2];
    const float* gnoise    = (const float*)d_in[3];
    const float* w00 = (const float*)d_in[4];
    const float* b00 = (const float*)d_in[5];
    const float* w01 = (const float*)d_in[6];
    const float* b01 = (const float*)d_in[7];
    const float* w10 = (const float*)d_in[8];
    const float* b10 = (const float*)d_in[9];
    const float* w11 = (const float*)d_in[10];
    const float* b11 = (const float*)d_in[11];
    const float* rw0 = (const float*)d_in[12];
    const float* rb0 = (const float*)d_in[13];
    const float* rw1 = (const float*)d_in[14];
    const float* rb1 = (const float*)d_in[15];
    float* out = (float*)d_out;

    cudaFuncSetAttribute(kC, cudaFuncAttributeMaxDynamicSharedMemorySize,
                         KC_SMEM_WORDS * 4);

    kA<<<(NTOT + 255)/256, 256>>>(proposals, gnoise);
    kB<<<dim3(KKEY/32, 4), 256>>>(kfeat, w00, w10);
    kC<<<NTOT/8, 256, KC_SMEM_WORDS * 4>>>(kxyz, w00, b00, w01, b01,
                                           w10, b10, w11, b11);
    kD<<<dim3(256/64, 96/16, KSPLIT), 256>>>(rw0);
    kE<<<96, 256>>>(rb0, rw1, rb1, out);
}